// round 7
// baseline (speedup 1.0000x reference)
#include <cuda_runtime.h>
#include <math.h>

#define N_NODES  100000
#define N_EDGES  1600000
#define IN_DIM   64
#define HIDDEN   128
#define N_GRAPHS 512

// ---------------- device scratch (referenced ONLY from device code) ----------------
__device__ __align__(16) int      g_off[N_NODES + 1];
__device__ __align__(16) int      g_cursor[N_NODES];
__device__ __align__(16) int      g_esrc[N_EDGES];
__device__ __align__(16) float    g_bufA[N_NODES * HIDDEN];
__device__ __align__(16) float    g_bufB[N_NODES * HIDDEN];
__device__ __align__(16) float    g_bufC[N_NODES * HIDDEN];
__device__ __align__(16) int      g_start[N_GRAPHS + 1];
__device__            unsigned    g_or;

// device-side buffer selector — NEVER pass g_buf* from host!
__device__ __forceinline__ float* bufptr(int i) {
    return (i == 0) ? g_bufA : ((i == 1) ? g_bufB : g_bufC);
}

// mode: 0 = int64 (low word, stride 2), 1 = int32, 2 = float32 bit patterns
__device__ __forceinline__ int dmode() {
    unsigned o = g_or;
    if (o == 0) return 0;
    if (o >= 0x3f000000u) return 2;
    return 1;
}
__device__ __forceinline__ int ld_idx(const unsigned* __restrict__ p, int idx, int mode) {
    if (mode == 0) return (int)p[2 * idx];
    unsigned w = p[idx];
    if (mode == 2) return (int)__uint_as_float(w);
    return (int)w;
}

__global__ void k_detect(const unsigned* __restrict__ ei32) {
    __shared__ unsigned sblk;
    if (threadIdx.x == 0) sblk = 0;
    __syncthreads();
    int e = blockIdx.x * blockDim.x + threadIdx.x;
    unsigned v = ei32[2 * e + 1];
    #pragma unroll
    for (int o = 16; o > 0; o >>= 1) v |= __shfl_xor_sync(0xFFFFFFFFu, v, o);
    if ((threadIdx.x & 31) == 0 && v) atomicOr(&sblk, v);
    __syncthreads();
    if (threadIdx.x == 0 && sblk) atomicOr(&g_or, sblk);
}

__global__ void k_zero_counts() {
    int i = blockIdx.x * blockDim.x + threadIdx.x;
    if (i == 0) g_or = 0;
    if (i <= N_NODES) g_off[i] = 0;
}

__global__ void k_count(const unsigned* __restrict__ ei32) {
    int e = blockIdx.x * blockDim.x + threadIdx.x;
    if (e < N_EDGES) {
        unsigned d = (unsigned)ld_idx(ei32, N_EDGES + e, dmode());
        if (d < N_NODES) atomicAdd(&g_off[d], 1);
    }
}

__global__ void k_scan() {
    __shared__ int sums[1024];
    const int T = 1024;
    int tid = threadIdx.x;
    const int per = (N_NODES + T - 1) / T;
    int b0 = tid * per;
    int b1 = b0 + per; if (b1 > N_NODES) b1 = N_NODES;
    if (b0 > N_NODES) b0 = N_NODES;
    int s = 0;
    for (int i = b0; i < b1; i++) s += g_off[i];
    sums[tid] = s;
    __syncthreads();
    for (int off = 1; off < T; off <<= 1) {
        int v = (tid >= off) ? sums[tid - off] : 0;
        __syncthreads();
        sums[tid] += v;
        __syncthreads();
    }
    int run = sums[tid] - s;
    for (int i = b0; i < b1; i++) {
        int c = g_off[i];
        g_off[i]    = run;
        g_cursor[i] = run;
        run += c;
    }
    if (tid == T - 1) g_off[N_NODES] = run;
}

__global__ void k_fill(const unsigned* __restrict__ ei32) {
    int e = blockIdx.x * blockDim.x + threadIdx.x;
    if (e < N_EDGES) {
        int mode = dmode();
        unsigned d = (unsigned)ld_idx(ei32, N_EDGES + e, mode);
        unsigned s = (unsigned)ld_idx(ei32, e, mode);
        if (d < N_NODES && s < N_NODES) {
            int p = atomicAdd(&g_cursor[d], 1);
            g_esrc[p] = (int)s;
        }
    }
}

// agg: out[n] = in[n] + sum_{e: dst==n} in[src_e]   (float4 lanes)
// ext used when inb < 0; otherwise device-resolved buffer.
template<int DIM>
__global__ void k_agg(const float* __restrict__ ext, int inb, int outb) {
    const float* in = (inb < 0) ? ext : bufptr(inb);
    float* out = bufptr(outb);
    const int C = DIM / 4;
    int idx = blockIdx.x * blockDim.x + threadIdx.x;
    if (idx >= N_NODES * C) return;
    int node = idx / C;
    int c    = (idx - node * C) * 4;
    float4 acc = *(const float4*)(in + node * DIM + c);
    int s = g_off[node], e = g_off[node + 1];
    for (int i = s; i < e; i++) {
        int src = g_esrc[i];
        float4 v = *(const float4*)(in + src * DIM + c);
        acc.x += v.x; acc.y += v.y; acc.z += v.z; acc.w += v.w;
    }
    *(float4*)(out + node * DIM + c) = acc;
}

// C = relu(A@W + b): 32-row tile per block, 256 threads, smem <= 32KB
template<int K>
__global__ void __launch_bounds__(256) k_gemm(int inb,
                                              const float* __restrict__ W,
                                              const float* __restrict__ bias,
                                              int outb) {
    const float* A = bufptr(inb);
    float* Cout = bufptr(outb);
    __shared__ float As[32][K];
    __shared__ float Ws[32][HIDDEN];
    int tid  = threadIdx.x;
    int row0 = blockIdx.x * 32;

    for (int i = tid; i < 32 * (K / 4); i += 256) {
        int r = i / (K / 4);
        int c = (i - r * (K / 4)) * 4;
        *(float4*)&As[r][c] = *(const float4*)(A + (row0 + r) * K + c);
    }

    float acc[4][4];
    #pragma unroll
    for (int i = 0; i < 4; i++)
        #pragma unroll
        for (int j = 0; j < 4; j++) acc[i][j] = 0.f;

    int tx = tid & 31;
    int ty = tid >> 5;

    for (int kc = 0; kc < K; kc += 32) {
        __syncthreads();
        for (int i = tid; i < 32 * (HIDDEN / 4); i += 256) {
            int r = i / (HIDDEN / 4);
            int c = (i - r * (HIDDEN / 4)) * 4;
            *(float4*)&Ws[r][c] = *(const float4*)(W + (kc + r) * HIDDEN + c);
        }
        __syncthreads();
        #pragma unroll 8
        for (int k2 = 0; k2 < 32; k2++) {
            float4 w = *(float4*)&Ws[k2][tx * 4];
            int k = kc + k2;
            #pragma unroll
            for (int i = 0; i < 4; i++) {
                float a = As[ty * 4 + i][k];
                acc[i][0] += a * w.x;
                acc[i][1] += a * w.y;
                acc[i][2] += a * w.z;
                acc[i][3] += a * w.w;
            }
        }
    }

    float4 bv = *(const float4*)(bias + tx * 4);
    #pragma unroll
    for (int i = 0; i < 4; i++) {
        int row = row0 + ty * 4 + i;
        float4 o;
        o.x = fmaxf(acc[i][0] + bv.x, 0.f);
        o.y = fmaxf(acc[i][1] + bv.y, 0.f);
        o.z = fmaxf(acc[i][2] + bv.z, 0.f);
        o.w = fmaxf(acc[i][3] + bv.w, 0.f);
        *(float4*)(Cout + row * HIDDEN + tx * 4) = o;
    }
}

__global__ void k_ranges(const unsigned* __restrict__ b32) {
    int g = blockIdx.x * blockDim.x + threadIdx.x;
    if (g > N_GRAPHS) return;
    int mode = dmode();
    int lo = 0, hi = N_NODES;
    while (lo < hi) {
        int mid = (lo + hi) >> 1;
        int bv = ld_idx(b32, mid, mode);
        if (bv < g) lo = mid + 1; else hi = mid;
    }
    g_start[g] = lo;
}

__global__ void __launch_bounds__(128) k_pool(const float* __restrict__ Wc,
                                              const float* __restrict__ bc,
                                              float* __restrict__ out) {
    int g = blockIdx.x;
    int d = threadIdx.x;
    int s = g_start[g], e = g_start[g + 1];
    float acc = 0.f;
    for (int n = s; n < e; n++) acc += g_bufC[n * HIDDEN + d];
    float cnt  = (float)(e - s);
    float mean = acc / fmaxf(cnt, 1.0f);
    float v = mean * Wc[d];

    __shared__ float red[128];
    red[d] = v;
    __syncthreads();
    #pragma unroll
    for (int off = 64; off > 0; off >>= 1) {
        if (d < off) red[d] += red[d + off];
        __syncthreads();
    }
    if (d == 0) out[g] = red[0] + bc[0];
}

// staged diagnostic: overwrites out ONLY on failure. m = CSR + 2·bufA + 4·bufB + 8·bufC
__global__ void __launch_bounds__(256) k_diag(float* __restrict__ out) {
    __shared__ float red[256];
    __shared__ int ok[4];
    int tid = threadIdx.x;
    if (tid == 0) ok[0] = (g_off[N_NODES] == N_EDGES) ? 1 : 0;

    for (int b = 0; b < 3; b++) {
        const float* buf = bufptr(b);
        float s = 0.f;
        for (int i = tid; i < 100000; i += 256) s += fabsf(buf[i]);
        red[tid] = s;
        __syncthreads();
        for (int o = 128; o > 0; o >>= 1) {
            if (tid < o) red[tid] += red[tid + o];
            __syncthreads();
        }
        if (tid == 0) { float t = red[0]; ok[b + 1] = (isfinite(t) && t > 0.f) ? 1 : 0; }
        __syncthreads();
    }

    int m = ok[0] + 2 * ok[1] + 4 * ok[2] + 8 * ok[3];
    if (m == 15) return;
    float V = exp10f((float)(4 + 2 * m));
    for (int g = tid; g < N_GRAPHS; g += 256) out[g] = V;
}

__global__ void k_mark(float* out, float v) {
    int g = blockIdx.x * blockDim.x + threadIdx.x;
    if (g < N_GRAPHS) out[g] = v;
}

// ---------------- launch ----------------
extern "C" void kernel_launch(void* const* d_in, const int* in_sizes, int n_in,
                              void* d_out, int out_size) {
    const float *x, *W1a, *b1a, *W1b, *b1b, *W2a, *b2a, *W2b, *b2b, *Wc, *bc;
    const unsigned *ei, *batch;
    float* out = (float*)d_out;

    if (in_sizes[0] == N_NODES * IN_DIM) {
        x     = (const float*)d_in[0];
        ei    = (const unsigned*)d_in[1];
        batch = (const unsigned*)d_in[2];
        W1a   = (const float*)d_in[3];   b1a = (const float*)d_in[4];
        W1b   = (const float*)d_in[5];   b1b = (const float*)d_in[6];
        W2a   = (const float*)d_in[7];   b2a = (const float*)d_in[8];
        W2b   = (const float*)d_in[9];   b2b = (const float*)d_in[10];
        Wc    = (const float*)d_in[11];  bc  = (const float*)d_in[12];
    } else {
        k_mark<<<2, 256>>>(out, __builtin_nanf(""));
        return;
    }

    // CSR build
    k_zero_counts<<<(N_NODES + 256) / 256, 256>>>();
    k_detect<<<N_EDGES / 256, 256>>>(ei);
    k_count<<<N_EDGES / 256, 256>>>(ei);
    k_scan<<<1, 1024>>>();
    k_fill<<<N_EDGES / 256, 256>>>(ei);

    // conv1: bufA = x + agg(x); bufB = relu(bufA W1a + b1a); bufC = relu(bufB W1b + b1b)
    k_agg<IN_DIM><<<(N_NODES * (IN_DIM / 4)) / 256, 256>>>(x, -1, 0);
    k_gemm<IN_DIM><<<N_NODES / 32, 256>>>(0, W1a, b1a, 1);
    k_gemm<HIDDEN><<<N_NODES / 32, 256>>>(1, W1b, b1b, 2);

    // conv2: bufA = bufC + agg(bufC); bufB = relu(...); bufC = relu(...)
    k_agg<HIDDEN><<<(N_NODES * (HIDDEN / 4)) / 256, 256>>>(nullptr, 2, 0);
    k_gemm<HIDDEN><<<N_NODES / 32, 256>>>(0, W2a, b2a, 1);
    k_gemm<HIDDEN><<<N_NODES / 32, 256>>>(1, W2b, b2b, 2);

    // pool + head
    k_ranges<<<3, 256>>>(batch);
    k_pool<<<N_GRAPHS, 128>>>(Wc, bc, out);

    // diagnostic override only on failure
    k_diag<<<1, 256>>>(out);
}